// round 8
// baseline (speedup 1.0000x reference)
#include <cuda_runtime.h>
#include <cuda_bf16.h>
#include <cuda_fp16.h>
#include <cstdint>
#include <math.h>

// Problem constants
#define NROWS   65536
#define DIMD    64
#define KCODES  1024
#define QELEMS  4194304

// Output layout (float32, concatenated in reference return order)
#define O_LOSS  0
#define O_QUANT 1
#define O_PERP  4194305
#define O_ENC   4194306
#define O_IDX   71303170

#define MARGIN  1.6e-3f
#define WLCAP   512

// ---------------- device scratch ----------------
__device__ float          g_embT[DIMD * KCODES];     // fp32 [d][k] for exact rescore
__device__ __nv_bfloat16  g_embB[KCODES * DIMD];     // bf16 [k][d] for MMA filter
__device__ float          g_B[KCODES];               // ||e_k||^2 exact order
__device__ __align__(16) int g_idx[NROWS];
__device__ int            g_hist[KCODES];
__device__ float          g_partial[4096];

// ---------------- asm helpers ----------------
__device__ __forceinline__ unsigned pack_bf16x2(float lo, float hi) {
    unsigned r;
    asm("cvt.rn.bf16x2.f32 %0, %1, %2;" : "=r"(r) : "f"(hi), "f"(lo));
    return r;
}
__device__ __forceinline__ void mma16816(float& c0, float& c1, float& c2, float& c3,
                                         unsigned a0, unsigned a1, unsigned a2, unsigned a3,
                                         unsigned b0, unsigned b1) {
    asm("mma.sync.aligned.m16n8k16.row.col.f32.bf16.bf16.f32 "
        "{%0,%1,%2,%3},{%4,%5,%6,%7},{%8,%9},{%0,%1,%2,%3};"
        : "+f"(c0), "+f"(c1), "+f"(c2), "+f"(c3)
        : "r"(a0), "r"(a1), "r"(a2), "r"(a3), "r"(b0), "r"(b1));
}
__device__ __forceinline__ void ldsm4(unsigned& r0, unsigned& r1, unsigned& r2, unsigned& r3,
                                      const void* p) {
    unsigned a = (unsigned)__cvta_generic_to_shared(p);
    asm volatile("ldmatrix.sync.aligned.m8n8.x4.shared.b16 {%0,%1,%2,%3}, [%4];"
                 : "=r"(r0), "=r"(r1), "=r"(r2), "=r"(r3) : "r"(a));
}
__device__ __forceinline__ void cp16(void* sp, const void* gp) {
    unsigned a = (unsigned)__cvta_generic_to_shared(sp);
    asm volatile("cp.async.cg.shared.global [%0], [%1], 16;" :: "r"(a), "l"(gp));
}
#define CP_COMMIT() asm volatile("cp.async.commit_group;")
#define CP_WAIT0()  asm volatile("cp.async.wait_group 0;")

// ---------------- prep: smem-tiled transpose + bf16 pack + norms ----------------
__global__ void __launch_bounds__(256)
prep_kernel(const float* __restrict__ emb) {
    __shared__ float tile[16][65];
    const int t = threadIdx.x, b = blockIdx.x;
    const float* src = emb + b * 16 * DIMD;
    #pragma unroll
    for (int i = 0; i < 4; ++i) {
        int id = i * 256 + t;                 // 0..1023
        tile[id >> 6][id & 63] = src[id];
    }
    __syncthreads();
    {
        __nv_bfloat162* dst = (__nv_bfloat162*)(g_embB + b * 1024);
        #pragma unroll
        for (int i = 0; i < 2; ++i) {
            int id2 = i * 256 + t;            // pair index 0..511
            int r = id2 >> 5, c2 = (id2 & 31) << 1;
            dst[id2] = __floats2bfloat162_rn(tile[r][c2], tile[r][c2 + 1]);
        }
    }
    {
        int d = t >> 2, kq = (t & 3) << 2;
        float4 v;
        v.x = tile[kq + 0][d];
        v.y = tile[kq + 1][d];
        v.z = tile[kq + 2][d];
        v.w = tile[kq + 3][d];
        *(float4*)(g_embT + d * KCODES + b * 16 + kq) = v;
    }
    if (t < 16) {
        float s = 0.f;
        #pragma unroll 16
        for (int d = 0; d < DIMD; ++d) {
            float v = tile[t][d];
            s = __fadd_rn(s, __fmul_rn(v, v));
        }
        g_B[b * 16 + t] = s;
    }
    if (b == 0) {
        #pragma unroll
        for (int i = t; i < KCODES; i += 256) g_hist[i] = 0;
    }
}

// ---------------- argmin smem layout (53.8 KB -> 4 blocks/SM, 1 wave) ----------
struct ArgSmem {
    uint4  Es[512];                     // 8 KB swizzled bf16 E-chunk (single buffer)
    float  Xs[128][65];                 // 33.3 KB fp32 X tile
    __half Cmin[32][128];               // 8 KB per-subchunk approx min (fp16 rd)
    float  rowA[128];
    float  rowlim[128];
    unsigned long long best[128];
    int    wl[WLCAP];
    int    nitems, wtake;
};
#define ARG_SMEM_BYTES sizeof(ArgSmem)

__device__ __forceinline__ void stageE(ArgSmem* sm, int c, int t) {
    const char* gb = (const char*)g_embB + (size_t)(c << 6) * 128;
    #pragma unroll
    for (int it = 0; it < 2; ++it) {
        int id = it * 256 + t;          // 0..511 cells
        int code = id >> 3, h = id & 7;
        int cell = (code << 3) | (h ^ (code & 7));
        cp16(&sm->Es[cell], gb + code * 128 + h * 16);
    }
}

// ---------------- argmin: MMA filter + exact rescore ----------------
__global__ void __launch_bounds__(256, 4)
argmin_kernel(const float* __restrict__ inputs, float* __restrict__ out) {
    extern __shared__ char raw[];
    ArgSmem* sm = (ArgSmem*)raw;

    const float INF = __int_as_float(0x7f800000);
    const int t = threadIdx.x;
    const int lane = t & 31;
    const int w = t >> 5;               // 8 warps
    const int g = lane >> 2, tig = lane & 3;
    const int blk = blockIdx.x;         // 512 blocks of 128 rows
    const int b = blk >> 3, sp0 = (blk & 7) << 7;
    const float* xb = inputs + (size_t)b * 65536 + sp0;

    if (t < 128) sm->best[t] = 0xFFFFFFFFFFFFFFFFULL;
    if (t == 0) { sm->nitems = 0; sm->wtake = 0; }

    // X tile: Xs[r][d]
    #pragma unroll
    for (int it = 0; it < 8; ++it) {
        int id4 = it * 256 + t;         // 0..2047
        int d = id4 >> 5, rq = id4 & 31;
        float4 v = *(const float4*)(xb + d * 1024 + (rq << 2));
        sm->Xs[4 * rq + 0][d] = v.x;
        sm->Xs[4 * rq + 1][d] = v.y;
        sm->Xs[4 * rq + 2][d] = v.z;
        sm->Xs[4 * rq + 3][d] = v.w;
    }
    stageE(sm, 0, t);
    CP_COMMIT();
    __syncthreads();

    // A-fragments held in regs for whole phase 1
    const int R = w << 4;
    unsigned afr[16];
    {
        const float* r0 = sm->Xs[R + g];
        const float* r1 = sm->Xs[R + 8 + g];
        #pragma unroll
        for (int kk = 0; kk < 4; ++kk) {
            int c0 = 16 * kk + 2 * tig;
            afr[4 * kk + 0] = pack_bf16x2(r0[c0],     r0[c0 + 1]);
            afr[4 * kk + 1] = pack_bf16x2(r1[c0],     r1[c0 + 1]);
            afr[4 * kk + 2] = pack_bf16x2(r0[c0 + 8], r0[c0 + 9]);
            afr[4 * kk + 3] = pack_bf16x2(r1[c0 + 8], r1[c0 + 9]);
        }
    }
    // exact ||x||^2, reference rounding order
    if (t < 128) {
        float a = 0.f;
        #pragma unroll 16
        for (int d = 0; d < DIMD; ++d) {
            float v = sm->Xs[t][d];
            a = __fadd_rn(a, __fmul_rn(v, v));
        }
        sm->rowA[t] = a;
    }

    // -------- Phase 1: bf16 MMA filter (single-buffered E) --------
    float sub_lo = INF, sub_hi = INF;
    for (int c = 0; c < 16; ++c) {
        CP_WAIT0();
        __syncthreads();
        const int kc = c << 6;
        #pragma unroll
        for (int ct = 0; ct < 8; ++ct) {
            const int C = ct << 3;
            float c0 = 0.f, c1 = 0.f, c2 = 0.f, c3 = 0.f;
            #pragma unroll
            for (int kk2 = 0; kk2 < 2; ++kk2) {
                int code = C + (lane & 7);
                int h = (kk2 << 2) + (lane >> 3);
                unsigned q0, q1, q2, q3;
                ldsm4(q0, q1, q2, q3, sm->Es + ((code << 3) | (h ^ (code & 7))));
                mma16816(c0, c1, c2, c3, afr[8 * kk2 + 0], afr[8 * kk2 + 1],
                         afr[8 * kk2 + 2], afr[8 * kk2 + 3], q0, q1);
                mma16816(c0, c1, c2, c3, afr[8 * kk2 + 4], afr[8 * kk2 + 5],
                         afr[8 * kk2 + 6], afr[8 * kk2 + 7], q2, q3);
            }
            float B0 = __ldg(&g_B[kc + C + 2 * tig]);
            float B1 = __ldg(&g_B[kc + C + 2 * tig + 1]);
            float v0 = fmaf(-2.f, c0, B0);
            float v1 = fmaf(-2.f, c1, B1);
            float v2 = fmaf(-2.f, c2, B0);
            float v3 = fmaf(-2.f, c3, B1);
            sub_lo = fminf(sub_lo, fminf(v0, v1));
            sub_hi = fminf(sub_hi, fminf(v2, v3));
            if ((ct & 3) == 3) {
                sub_lo = fminf(sub_lo, __shfl_xor_sync(0xffffffffu, sub_lo, 1));
                sub_lo = fminf(sub_lo, __shfl_xor_sync(0xffffffffu, sub_lo, 2));
                sub_hi = fminf(sub_hi, __shfl_xor_sync(0xffffffffu, sub_hi, 1));
                sub_hi = fminf(sub_hi, __shfl_xor_sync(0xffffffffu, sub_hi, 2));
                int s = (c << 1) | (ct >> 2);
                if (tig == 0) {
                    sm->Cmin[s][R + g]     = __float2half_rd(sub_lo);
                    sm->Cmin[s][R + 8 + g] = __float2half_rd(sub_hi);
                }
                sub_lo = INF; sub_hi = INF;
            }
        }
        __syncthreads();                 // all consumers done before overwrite
        if (c + 1 < 16) { stageE(sm, c + 1, t); CP_COMMIT(); }
    }

    // -------- Phase 2: worklist + exact rescore --------
    if (t < 128) {
        float m = INF;
        #pragma unroll
        for (int s = 0; s < 32; ++s) m = fminf(m, __half2float(sm->Cmin[s][t]));
        sm->rowlim[t] = m + MARGIN;
    }
    __syncthreads();
    if (t < 128) {
        float lim = sm->rowlim[t];
        #pragma unroll 4
        for (int s = 0; s < 32; ++s) {
            if (__half2float(sm->Cmin[s][t]) <= lim) {
                int pos = atomicAdd(&sm->nitems, 1);
                if (pos < WLCAP) {
                    sm->wl[pos] = (t << 5) | s;
                } else {
                    // overflow safety net: exact scalar rescore (inert normally)
                    for (int kk = 0; kk < 32; ++kk) {
                        int k = (s << 5) + kk;
                        float dot = 0.f;
                        for (int d = 0; d < DIMD; ++d)
                            dot = __fmaf_rn(sm->Xs[t][d], g_embT[(d << 10) + k], dot);
                        float dist = __fsub_rn(__fadd_rn(sm->rowA[t], g_B[k]),
                                               __fmul_rn(2.f, dot));
                        unsigned long long pkv =
                            ((unsigned long long)__float_as_uint(dist) << 32) | (unsigned)k;
                        atomicMin(&sm->best[t], pkv);
                    }
                }
            }
        }
    }
    __syncthreads();
    const int NI = min(sm->nitems, WLCAP);
    while (true) {
        int i = 0;
        if (lane == 0) i = atomicAdd(&sm->wtake, 1);
        i = __shfl_sync(0xffffffffu, i, 0);
        if (i >= NI) break;
        int item = sm->wl[i];
        int row = item >> 5, s = item & 31;
        int k = (s << 5) + lane;
        const float* ep = g_embT + k;
        float dot = 0.f;
        #pragma unroll 16
        for (int d = 0; d < DIMD; ++d)
            dot = __fmaf_rn(sm->Xs[row][d], ep[d << 10], dot);
        float dist = __fsub_rn(__fadd_rn(sm->rowA[row], g_B[k]), __fmul_rn(2.f, dot));
        unsigned long long pk = ((unsigned long long)__float_as_uint(dist) << 32) | (unsigned)k;
        #pragma unroll
        for (int off = 16; off > 0; off >>= 1) {
            unsigned long long o = __shfl_down_sync(0xffffffffu, pk, off);
            if (o < pk) pk = o;
        }
        if (lane == 0) atomicMin(&sm->best[row], pk);
    }
    __syncthreads();
    if (t < 128) {
        int k = (int)(unsigned)(sm->best[t] & 0xffffffffULL);
        int n = (blk << 7) + t;
        g_idx[n] = k;
        out[(size_t)O_IDX + n] = (float)k;
        atomicAdd(&g_hist[k], 1);
    }
}

// ---------------- quantized gather + MSE partials (scalar, coalesced) --------
// 4096 blocks x 256 threads; block handles 1024 consecutive NCHW elements,
// thread does 4 strided-by-256 elements (all scalar, fully coalesced; the
// O_QUANT=1 output offset forbids vector stores).
__global__ void __launch_bounds__(256)
quant_kernel(const float* __restrict__ inputs, const float* __restrict__ emb,
             float* __restrict__ out) {
    const int base = blockIdx.x * 1024;
    float s = 0.f;
    #pragma unroll
    for (int i = 0; i < 4; ++i) {
        int e  = base + i * 256 + threadIdx.x;
        int sp = e & 1023;
        int d  = (e >> 10) & 63;
        int b  = e >> 16;
        int id = g_idx[(b << 10) + sp];
        float q = __ldg(&emb[id * DIMD + d]);
        float x = inputs[e];
        out[O_QUANT + e] = q;
        float df = q - x;
        s = __fmaf_rn(df, df, s);
    }
    #pragma unroll
    for (int off = 16; off > 0; off >>= 1)
        s += __shfl_down_sync(0xffffffffu, s, off);
    __shared__ float ws[8];
    if ((threadIdx.x & 31) == 0) ws[threadIdx.x >> 5] = s;
    __syncthreads();
    if (threadIdx.x == 0) {
        float tot = 0.f;
        #pragma unroll
        for (int i = 0; i < 8; ++i) tot += ws[i];
        g_partial[blockIdx.x] = tot;
    }
}

// ---------------- scalars: loss + perplexity ----------------
__global__ void __launch_bounds__(1024)
finalize_kernel(float* __restrict__ out) {
    __shared__ float ws[32];
    int t = threadIdx.x, lane = t & 31, w = t >> 5;
    float s = g_partial[t] + g_partial[t + 1024] + g_partial[t + 2048] + g_partial[t + 3072];
    #pragma unroll
    for (int off = 16; off > 0; off >>= 1) s += __shfl_down_sync(0xffffffffu, s, off);
    if (lane == 0) ws[w] = s;
    __syncthreads();
    if (t < 32) {
        float v = ws[t];
        #pragma unroll
        for (int off = 16; off > 0; off >>= 1) v += __shfl_down_sync(0xffffffffu, v, off);
        if (t == 0) ws[0] = v;
    }
    __syncthreads();
    float S = ws[0];
    __syncthreads();
    float p = (float)g_hist[t] * (1.0f / 65536.0f);
    float h = p * logf(p + 1e-10f);
    #pragma unroll
    for (int off = 16; off > 0; off >>= 1) h += __shfl_down_sync(0xffffffffu, h, off);
    if (lane == 0) ws[w] = h;
    __syncthreads();
    if (t < 32) {
        float v = ws[t];
        #pragma unroll
        for (int off = 16; off > 0; off >>= 1) v += __shfl_down_sync(0xffffffffu, v, off);
        if (t == 0) {
            float perp = expf(-v);
            float mse  = S * (1.0f / (float)QELEMS);
            float loss = __fadd_rn(mse, __fmul_rn(0.25f, mse));
            float dv   = __fdiv_rn(__fmul_rn(0.1f, __fsub_rn(1024.0f, perp)), 1024.0f);
            out[O_LOSS] = __fadd_rn(loss, dv);
            out[O_PERP] = perp;
        }
    }
}

// ---------------- one-hot encodings (268 MB streaming write) ----------------
__global__ void enc_kernel(float* __restrict__ out) {
    float2* o2 = (float2*)(out + O_ENC);       // O_ENC even -> 8B aligned
    size_t base = (size_t)blockIdx.x * 2048 + threadIdx.x;
    #pragma unroll
    for (int i = 0; i < 8; ++i) {
        size_t p = base + (size_t)i * 256;
        int linear = (int)(p << 1);
        int row = linear >> 10;
        int col = linear & 1023;
        int id  = g_idx[row];
        float2 v;
        v.x = (col     == id) ? 1.f : 0.f;
        v.y = (col + 1 == id) ? 1.f : 0.f;
        o2[p] = v;
    }
}

// ---------------- launch ----------------
extern "C" void kernel_launch(void* const* d_in, const int* in_sizes, int n_in,
                              void* d_out, int out_size) {
    const float* inputs = (const float*)d_in[0];
    const float* emb    = (const float*)d_in[1];
    if (n_in >= 2 && in_sizes[0] == KCODES * DIMD) {
        inputs = (const float*)d_in[1];
        emb    = (const float*)d_in[0];
    }
    float* out = (float*)d_out;

    cudaFuncSetAttribute(argmin_kernel, cudaFuncAttributeMaxDynamicSharedMemorySize,
                         (int)ARG_SMEM_BYTES);

    prep_kernel<<<64, 256>>>(emb);
    argmin_kernel<<<512, 256, ARG_SMEM_BYTES>>>(inputs, out);
    quant_kernel<<<4096, 256>>>(inputs, emb, out);
    finalize_kernel<<<1, 1024>>>(out);
    enc_kernel<<<16384, 256>>>(out);
}

// round 9
// speedup vs baseline: 1.2873x; 1.2873x over previous
#include <cuda_runtime.h>
#include <cuda_bf16.h>
#include <cstdint>
#include <math.h>

// Problem constants
#define NROWS   65536
#define DIMD    64
#define KCODES  1024
#define QELEMS  4194304

// Output layout (float32, concatenated in reference return order)
#define O_LOSS  0
#define O_QUANT 1
#define O_PERP  4194305
#define O_ENC   4194306
#define O_IDX   71303170

#define MARGIN  1.5e-3f
#define WLCAP   1536

// ---------------- device scratch ----------------
__device__ float          g_embT[DIMD * KCODES];       // fp32 [d][k] (fallback path)
__device__ float4         g_embT4[16 * KCODES];        // fp32 [d4][k] -> 4 d's per LDG.128
__device__ __nv_bfloat16  g_embB[KCODES * DIMD];       // bf16 [k][d] for MMA filter
__device__ float          g_B[KCODES];                 // ||e_k||^2 exact order
__device__ __align__(16) int g_idx[NROWS];
__device__ int            g_hist[KCODES];
__device__ float          g_partial[4096];

// ---------------- asm helpers ----------------
__device__ __forceinline__ unsigned pack_bf16x2(float lo, float hi) {
    unsigned r;
    asm("cvt.rn.bf16x2.f32 %0, %1, %2;" : "=r"(r) : "f"(hi), "f"(lo));
    return r;
}
__device__ __forceinline__ void mma16816(float& c0, float& c1, float& c2, float& c3,
                                         unsigned a0, unsigned a1, unsigned a2, unsigned a3,
                                         unsigned b0, unsigned b1) {
    asm("mma.sync.aligned.m16n8k16.row.col.f32.bf16.bf16.f32 "
        "{%0,%1,%2,%3},{%4,%5,%6,%7},{%8,%9},{%0,%1,%2,%3};"
        : "+f"(c0), "+f"(c1), "+f"(c2), "+f"(c3)
        : "r"(a0), "r"(a1), "r"(a2), "r"(a3), "r"(b0), "r"(b1));
}
__device__ __forceinline__ void ldsm4(unsigned& r0, unsigned& r1, unsigned& r2, unsigned& r3,
                                      const void* p) {
    unsigned a = (unsigned)__cvta_generic_to_shared(p);
    asm volatile("ldmatrix.sync.aligned.m8n8.x4.shared.b16 {%0,%1,%2,%3}, [%4];"
                 : "=r"(r0), "=r"(r1), "=r"(r2), "=r"(r3) : "r"(a));
}
__device__ __forceinline__ void cp16(void* sp, const void* gp) {
    unsigned a = (unsigned)__cvta_generic_to_shared(sp);
    asm volatile("cp.async.cg.shared.global [%0], [%1], 16;" :: "r"(a), "l"(gp));
}
#define CP_COMMIT() asm volatile("cp.async.commit_group;")
#define CP_WAIT0()  asm volatile("cp.async.wait_group 0;")

// ---------------- prep: transpose + bf16 pack + float4 layout + norms --------
__global__ void __launch_bounds__(256)
prep_kernel(const float* __restrict__ emb) {
    __shared__ float tile[16][65];
    const int t = threadIdx.x, b = blockIdx.x;      // 64 blocks, codes [16b,16b+16)
    const float* src = emb + b * 16 * DIMD;
    #pragma unroll
    for (int i = 0; i < 4; ++i) {
        int id = i * 256 + t;                 // 0..1023
        tile[id >> 6][id & 63] = src[id];
    }
    __syncthreads();
    // bf16 pack, linear layout identical to emb
    {
        __nv_bfloat162* dst = (__nv_bfloat162*)(g_embB + b * 1024);
        #pragma unroll
        for (int i = 0; i < 2; ++i) {
            int id2 = i * 256 + t;            // pair index 0..511
            int r = id2 >> 5, c2 = (id2 & 31) << 1;
            dst[id2] = __floats2bfloat162_rn(tile[r][c2], tile[r][c2 + 1]);
        }
    }
    // fp32 transpose: embT[d][16b + k]
    {
        int d = t >> 2, kq = (t & 3) << 2;
        float4 v;
        v.x = tile[kq + 0][d];
        v.y = tile[kq + 1][d];
        v.z = tile[kq + 2][d];
        v.w = tile[kq + 3][d];
        *(float4*)(g_embT + d * KCODES + b * 16 + kq) = v;
    }
    // float4 layout for rescore: embT4[d4][k] = emb[k][4d4..4d4+3]
    {
        int code = t & 15, d4 = t >> 4;       // 256 cells: coalesced over code
        float4 v;
        v.x = tile[code][4 * d4 + 0];
        v.y = tile[code][4 * d4 + 1];
        v.z = tile[code][4 * d4 + 2];
        v.w = tile[code][4 * d4 + 3];
        g_embT4[(d4 << 10) + b * 16 + code] = v;
    }
    // exact norms (sequential fl(e*e) adds)
    if (t < 16) {
        float s = 0.f;
        #pragma unroll 16
        for (int d = 0; d < DIMD; ++d) {
            float v = tile[t][d];
            s = __fadd_rn(s, __fmul_rn(v, v));
        }
        g_B[b * 16 + t] = s;
    }
    if (b == 0) {
        #pragma unroll
        for (int i = t; i < KCODES; i += 256) g_hist[i] = 0;
    }
}

// ---------------- argmin smem layout (round-6 structure) ----------------
struct ArgSmem {
    uint4 Es[2][512];                   // 16 KB swizzled bf16 E-chunk, dbl-buffered
    float Xs[128][65];                  // fp32 X tile
    float Cmin[32][128];                // per-subchunk approx min
    float rowA[128];
    float rowlim[128];
    unsigned long long best[128];
    int   wl[WLCAP];
    int   nitems, wtake;
};
#define ARG_SMEM_BYTES sizeof(ArgSmem)

__device__ __forceinline__ void stageE(ArgSmem* sm, int c, int t) {
    const char* gb = (const char*)g_embB + (size_t)(c << 6) * 128;
    #pragma unroll
    for (int it = 0; it < 2; ++it) {
        int id = it * 256 + t;          // 0..511 cells
        int code = id >> 3, h = id & 7;
        int cell = (code << 3) | (h ^ (code & 7));
        cp16(&sm->Es[c & 1][cell], gb + code * 128 + h * 16);
    }
}

// ---------------- argmin: MMA filter + exact rescore ----------------
__global__ void __launch_bounds__(256)
argmin_kernel(const float* __restrict__ inputs, float* __restrict__ out) {
    extern __shared__ char raw[];
    ArgSmem* sm = (ArgSmem*)raw;

    const float INF = __int_as_float(0x7f800000);
    const int t = threadIdx.x;
    const int lane = t & 31;
    const int w = t >> 5;               // 8 warps
    const int g = lane >> 2, tig = lane & 3;
    const int blk = blockIdx.x;         // 512 blocks of 128 rows
    const int b = blk >> 3, sp0 = (blk & 7) << 7;
    const float* xb = inputs + (size_t)b * 65536 + sp0;

    if (t < 128) sm->best[t] = 0xFFFFFFFFFFFFFFFFULL;
    if (t == 0) { sm->nitems = 0; sm->wtake = 0; }

    // X tile: Xs[r][d]
    #pragma unroll
    for (int it = 0; it < 8; ++it) {
        int id4 = it * 256 + t;         // 0..2047
        int d = id4 >> 5, rq = id4 & 31;
        float4 v = *(const float4*)(xb + d * 1024 + (rq << 2));
        sm->Xs[4 * rq + 0][d] = v.x;
        sm->Xs[4 * rq + 1][d] = v.y;
        sm->Xs[4 * rq + 2][d] = v.z;
        sm->Xs[4 * rq + 3][d] = v.w;
    }
    stageE(sm, 0, t);
    CP_COMMIT();
    __syncthreads();

    // A-fragments held in regs for whole phase 1
    const int R = w << 4;
    unsigned afr[16];
    {
        const float* r0 = sm->Xs[R + g];
        const float* r1 = sm->Xs[R + 8 + g];
        #pragma unroll
        for (int kk = 0; kk < 4; ++kk) {
            int c0 = 16 * kk + 2 * tig;
            afr[4 * kk + 0] = pack_bf16x2(r0[c0],     r0[c0 + 1]);
            afr[4 * kk + 1] = pack_bf16x2(r1[c0],     r1[c0 + 1]);
            afr[4 * kk + 2] = pack_bf16x2(r0[c0 + 8], r0[c0 + 9]);
            afr[4 * kk + 3] = pack_bf16x2(r1[c0 + 8], r1[c0 + 9]);
        }
    }
    // exact ||x||^2, reference rounding order
    if (t < 128) {
        float a = 0.f;
        #pragma unroll 16
        for (int d = 0; d < DIMD; ++d) {
            float v = sm->Xs[t][d];
            a = __fadd_rn(a, __fmul_rn(v, v));
        }
        sm->rowA[t] = a;
    }

    // -------- Phase 1: bf16 MMA filter (double-buffered E) --------
    float sub_lo = INF, sub_hi = INF;
    for (int c = 0; c < 16; ++c) {
        CP_WAIT0();
        __syncthreads();
        if (c + 1 < 16) { stageE(sm, c + 1, t); CP_COMMIT(); }
        const uint4* Eb = sm->Es[c & 1];
        const int kc = c << 6;
        #pragma unroll
        for (int ct = 0; ct < 8; ++ct) {
            const int C = ct << 3;
            float c0 = 0.f, c1 = 0.f, c2 = 0.f, c3 = 0.f;
            #pragma unroll
            for (int kk2 = 0; kk2 < 2; ++kk2) {
                int code = C + (lane & 7);
                int h = (kk2 << 2) + (lane >> 3);
                unsigned q0, q1, q2, q3;
                ldsm4(q0, q1, q2, q3, Eb + ((code << 3) | (h ^ (code & 7))));
                mma16816(c0, c1, c2, c3, afr[8 * kk2 + 0], afr[8 * kk2 + 1],
                         afr[8 * kk2 + 2], afr[8 * kk2 + 3], q0, q1);
                mma16816(c0, c1, c2, c3, afr[8 * kk2 + 4], afr[8 * kk2 + 5],
                         afr[8 * kk2 + 6], afr[8 * kk2 + 7], q2, q3);
            }
            float B0 = __ldg(&g_B[kc + C + 2 * tig]);
            float B1 = __ldg(&g_B[kc + C + 2 * tig + 1]);
            float v0 = fmaf(-2.f, c0, B0);
            float v1 = fmaf(-2.f, c1, B1);
            float v2 = fmaf(-2.f, c2, B0);
            float v3 = fmaf(-2.f, c3, B1);
            sub_lo = fminf(sub_lo, fminf(v0, v1));
            sub_hi = fminf(sub_hi, fminf(v2, v3));
            if ((ct & 3) == 3) {
                sub_lo = fminf(sub_lo, __shfl_xor_sync(0xffffffffu, sub_lo, 1));
                sub_lo = fminf(sub_lo, __shfl_xor_sync(0xffffffffu, sub_lo, 2));
                sub_hi = fminf(sub_hi, __shfl_xor_sync(0xffffffffu, sub_hi, 1));
                sub_hi = fminf(sub_hi, __shfl_xor_sync(0xffffffffu, sub_hi, 2));
                int s = (c << 1) | (ct >> 2);
                if (tig == 0) {
                    sm->Cmin[s][R + g]     = sub_lo;
                    sm->Cmin[s][R + 8 + g] = sub_hi;
                }
                sub_lo = INF; sub_hi = INF;
            }
        }
        __syncthreads();   // protect Es buffer before next chunk's load overlaps
    }

    // -------- Phase 2: worklist + exact rescore (float4 codebook) --------
    if (t < 128) {
        float m = INF;
        #pragma unroll
        for (int s = 0; s < 32; ++s) m = fminf(m, sm->Cmin[s][t]);
        sm->rowlim[t] = m + MARGIN;
    }
    __syncthreads();
    if (t < 128) {
        float lim = sm->rowlim[t];
        #pragma unroll 4
        for (int s = 0; s < 32; ++s) {
            if (sm->Cmin[s][t] <= lim) {
                int pos = atomicAdd(&sm->nitems, 1);
                if (pos < WLCAP) {
                    sm->wl[pos] = (t << 5) | s;
                } else {
                    // overflow safety net: exact scalar rescore (inert normally)
                    for (int kk = 0; kk < 32; ++kk) {
                        int k = (s << 5) + kk;
                        float dot = 0.f;
                        for (int d = 0; d < DIMD; ++d)
                            dot = __fmaf_rn(sm->Xs[t][d], g_embT[(d << 10) + k], dot);
                        float dist = __fsub_rn(__fadd_rn(sm->rowA[t], g_B[k]),
                                               __fmul_rn(2.f, dot));
                        unsigned long long pkv =
                            ((unsigned long long)__float_as_uint(dist) << 32) | (unsigned)k;
                        atomicMin(&sm->best[t], pkv);
                    }
                }
            }
        }
    }
    __syncthreads();
    const int NI = min(sm->nitems, WLCAP);
    while (true) {
        int i = 0;
        if (lane == 0) i = atomicAdd(&sm->wtake, 1);
        i = __shfl_sync(0xffffffffu, i, 0);
        if (i >= NI) break;
        int item = sm->wl[i];
        int row = item >> 5, s = item & 31;
        int k = (s << 5) + lane;
        const float* xr = sm->Xs[row];
        float dot = 0.f;
        // sequential d order preserved: d = 4*d4 + {0,1,2,3}
        #pragma unroll
        for (int d4 = 0; d4 < 16; ++d4) {
            float4 e = __ldg(&g_embT4[(d4 << 10) + k]);
            dot = __fmaf_rn(xr[4 * d4 + 0], e.x, dot);
            dot = __fmaf_rn(xr[4 * d4 + 1], e.y, dot);
            dot = __fmaf_rn(xr[4 * d4 + 2], e.z, dot);
            dot = __fmaf_rn(xr[4 * d4 + 3], e.w, dot);
        }
        float dist = __fsub_rn(__fadd_rn(sm->rowA[row], g_B[k]), __fmul_rn(2.f, dot));
        unsigned long long pk = ((unsigned long long)__float_as_uint(dist) << 32) | (unsigned)k;
        #pragma unroll
        for (int off = 16; off > 0; off >>= 1) {
            unsigned long long o = __shfl_down_sync(0xffffffffu, pk, off);
            if (o < pk) pk = o;
        }
        if (lane == 0) atomicMin(&sm->best[row], pk);
    }
    __syncthreads();
    if (t < 128) {
        int k = (int)(unsigned)(sm->best[t] & 0xffffffffULL);
        int n = (blk << 7) + t;
        g_idx[n] = k;
        out[(size_t)O_IDX + n] = (float)k;
        atomicAdd(&g_hist[k], 1);
    }
}

// ---------------- quantized gather + MSE partials (scalar, coalesced) --------
__global__ void __launch_bounds__(256)
quant_kernel(const float* __restrict__ inputs, const float* __restrict__ emb,
             float* __restrict__ out) {
    const int base = blockIdx.x * 1024;
    float s = 0.f;
    #pragma unroll
    for (int i = 0; i < 4; ++i) {
        int e  = base + i * 256 + threadIdx.x;
        int sp = e & 1023;
        int d  = (e >> 10) & 63;
        int b  = e >> 16;
        int id = g_idx[(b << 10) + sp];
        float q = __ldg(&emb[id * DIMD + d]);
        float x = inputs[e];
        out[O_QUANT + e] = q;
        float df = q - x;
        s = __fmaf_rn(df, df, s);
    }
    #pragma unroll
    for (int off = 16; off > 0; off >>= 1)
        s += __shfl_down_sync(0xffffffffu, s, off);
    __shared__ float ws[8];
    if ((threadIdx.x & 31) == 0) ws[threadIdx.x >> 5] = s;
    __syncthreads();
    if (threadIdx.x == 0) {
        float tot = 0.f;
        #pragma unroll
        for (int i = 0; i < 8; ++i) tot += ws[i];
        g_partial[blockIdx.x] = tot;
    }
}

// ---------------- scalars: loss + perplexity ----------------
__global__ void __launch_bounds__(1024)
finalize_kernel(float* __restrict__ out) {
    __shared__ float ws[32];
    int t = threadIdx.x, lane = t & 31, w = t >> 5;
    float s = g_partial[t] + g_partial[t + 1024] + g_partial[t + 2048] + g_partial[t + 3072];
    #pragma unroll
    for (int off = 16; off > 0; off >>= 1) s += __shfl_down_sync(0xffffffffu, s, off);
    if (lane == 0) ws[w] = s;
    __syncthreads();
    if (t < 32) {
        float v = ws[t];
        #pragma unroll
        for (int off = 16; off > 0; off >>= 1) v += __shfl_down_sync(0xffffffffu, v, off);
        if (t == 0) ws[0] = v;
    }
    __syncthreads();
    float S = ws[0];
    __syncthreads();
    float p = (float)g_hist[t] * (1.0f / 65536.0f);
    float h = p * logf(p + 1e-10f);
    #pragma unroll
    for (int off = 16; off > 0; off >>= 1) h += __shfl_down_sync(0xffffffffu, h, off);
    if (lane == 0) ws[w] = h;
    __syncthreads();
    if (t < 32) {
        float v = ws[t];
        #pragma unroll
        for (int off = 16; off > 0; off >>= 1) v += __shfl_down_sync(0xffffffffu, v, off);
        if (t == 0) {
            float perp = expf(-v);
            float mse  = S * (1.0f / (float)QELEMS);
            float loss = __fadd_rn(mse, __fmul_rn(0.25f, mse));
            float dv   = __fdiv_rn(__fmul_rn(0.1f, __fsub_rn(1024.0f, perp)), 1024.0f);
            out[O_LOSS] = __fadd_rn(loss, dv);
            out[O_PERP] = perp;
        }
    }
}

// ---------------- one-hot encodings (268 MB streaming write) ----------------
__global__ void enc_kernel(float* __restrict__ out) {
    float2* o2 = (float2*)(out + O_ENC);       // O_ENC even -> 8B aligned
    size_t base = (size_t)blockIdx.x * 2048 + threadIdx.x;
    #pragma unroll
    for (int i = 0; i < 8; ++i) {
        size_t p = base + (size_t)i * 256;
        int linear = (int)(p << 1);
        int row = linear >> 10;
        int col = linear & 1023;
        int id  = g_idx[row];
        float2 v;
        v.x = (col     == id) ? 1.f : 0.f;
        v.y = (col + 1 == id) ? 1.f : 0.f;
        o2[p] = v;
    }
}

// ---------------- launch ----------------
extern "C" void kernel_launch(void* const* d_in, const int* in_sizes, int n_in,
                              void* d_out, int out_size) {
    const float* inputs = (const float*)d_in[0];
    const float* emb    = (const float*)d_in[1];
    if (n_in >= 2 && in_sizes[0] == KCODES * DIMD) {
        inputs = (const float*)d_in[1];
        emb    = (const float*)d_in[0];
    }
    float* out = (float*)d_out;

    cudaFuncSetAttribute(argmin_kernel, cudaFuncAttributeMaxDynamicSharedMemorySize,
                         (int)ARG_SMEM_BYTES);

    prep_kernel<<<64, 256>>>(emb);
    argmin_kernel<<<512, 256, ARG_SMEM_BYTES>>>(inputs, out);
    quant_kernel<<<4096, 256>>>(inputs, emb, out);
    finalize_kernel<<<1, 1024>>>(out);
    enc_kernel<<<16384, 256>>>(out);
}

// round 11
// speedup vs baseline: 1.4519x; 1.1279x over previous
#include <cuda_runtime.h>
#include <cuda_bf16.h>
#include <cstdint>
#include <math.h>

// Problem constants
#define NROWS   65536
#define DIMD    64
#define KCODES  1024
#define QELEMS  4194304

// Output layout (float32, concatenated in reference return order)
#define O_LOSS  0
#define O_QUANT 1
#define O_PERP  4194305
#define O_ENC   4194306
#define O_IDX   71303170

#define MARGIN  1.5e-3f
#define WLCAP   1536

// ---------------- device scratch ----------------
__device__ float          g_embT[DIMD * KCODES];       // fp32 [d][k] (fallback path)
__device__ float4         g_embT4[16 * KCODES];        // fp32 [d4][k] -> 4 d's per LDG.128
__device__ __nv_bfloat16  g_embB[KCODES * DIMD];       // bf16 [k][d] for MMA filter
__device__ float          g_B[KCODES];                 // ||e_k||^2 exact order
__device__ __align__(16) int g_idx[NROWS];
__device__ int            g_hist[KCODES];
__device__ float          g_partial[4096];

// ---------------- asm helpers ----------------
__device__ __forceinline__ unsigned pack_bf16x2(float lo, float hi) {
    unsigned r;
    asm("cvt.rn.bf16x2.f32 %0, %1, %2;" : "=r"(r) : "f"(hi), "f"(lo));
    return r;
}
__device__ __forceinline__ void mma16816(float& c0, float& c1, float& c2, float& c3,
                                         unsigned a0, unsigned a1, unsigned a2, unsigned a3,
                                         unsigned b0, unsigned b1) {
    asm("mma.sync.aligned.m16n8k16.row.col.f32.bf16.bf16.f32 "
        "{%0,%1,%2,%3},{%4,%5,%6,%7},{%8,%9},{%0,%1,%2,%3};"
        : "+f"(c0), "+f"(c1), "+f"(c2), "+f"(c3)
        : "r"(a0), "r"(a1), "r"(a2), "r"(a3), "r"(b0), "r"(b1));
}
__device__ __forceinline__ void ldsm4(unsigned& r0, unsigned& r1, unsigned& r2, unsigned& r3,
                                      const void* p) {
    unsigned a = (unsigned)__cvta_generic_to_shared(p);
    asm volatile("ldmatrix.sync.aligned.m8n8.x4.shared.b16 {%0,%1,%2,%3}, [%4];"
                 : "=r"(r0), "=r"(r1), "=r"(r2), "=r"(r3) : "r"(a));
}
__device__ __forceinline__ void cp16(void* sp, const void* gp) {
    unsigned a = (unsigned)__cvta_generic_to_shared(sp);
    asm volatile("cp.async.cg.shared.global [%0], [%1], 16;" :: "r"(a), "l"(gp));
}
#define CP_COMMIT() asm volatile("cp.async.commit_group;")
#define CP_WAIT0()  asm volatile("cp.async.wait_group 0;")

// ---------------- prep: transpose + bf16 pack + float4 layout + norms --------
__global__ void __launch_bounds__(256)
prep_kernel(const float* __restrict__ emb) {
    __shared__ float tile[16][65];
    const int t = threadIdx.x, b = blockIdx.x;      // 64 blocks, codes [16b,16b+16)
    const float* src = emb + b * 16 * DIMD;
    #pragma unroll
    for (int i = 0; i < 4; ++i) {
        int id = i * 256 + t;                 // 0..1023
        tile[id >> 6][id & 63] = src[id];
    }
    __syncthreads();
    // bf16 pack, linear layout identical to emb
    {
        __nv_bfloat162* dst = (__nv_bfloat162*)(g_embB + b * 1024);
        #pragma unroll
        for (int i = 0; i < 2; ++i) {
            int id2 = i * 256 + t;            // pair index 0..511
            int r = id2 >> 5, c2 = (id2 & 31) << 1;
            dst[id2] = __floats2bfloat162_rn(tile[r][c2], tile[r][c2 + 1]);
        }
    }
    // fp32 transpose: embT[d][16b + k]
    {
        int d = t >> 2, kq = (t & 3) << 2;
        float4 v;
        v.x = tile[kq + 0][d];
        v.y = tile[kq + 1][d];
        v.z = tile[kq + 2][d];
        v.w = tile[kq + 3][d];
        *(float4*)(g_embT + d * KCODES + b * 16 + kq) = v;
    }
    // float4 layout for rescore: embT4[d4][k] = emb[k][4d4..4d4+3]
    {
        int code = t & 15, d4 = t >> 4;       // 256 cells: coalesced over code
        float4 v;
        v.x = tile[code][4 * d4 + 0];
        v.y = tile[code][4 * d4 + 1];
        v.z = tile[code][4 * d4 + 2];
        v.w = tile[code][4 * d4 + 3];
        g_embT4[(d4 << 10) + b * 16 + code] = v;
    }
    // exact norms (sequential fl(e*e) adds)
    if (t < 16) {
        float s = 0.f;
        #pragma unroll 16
        for (int d = 0; d < DIMD; ++d) {
            float v = tile[t][d];
            s = __fadd_rn(s, __fmul_rn(v, v));
        }
        g_B[b * 16 + t] = s;
    }
    if (b == 0) {
        #pragma unroll
        for (int i = t; i < KCODES; i += 256) g_hist[i] = 0;
    }
}

// ---------------- argmin smem layout ----------------
struct ArgSmem {
    uint4 Es[2][512];                   // 16 KB swizzled bf16 E-chunk, dbl-buffered
    float Xs[128][65];                  // fp32 X tile
    float Cmin[32][128];                // per-subchunk approx min
    float rowA[128];
    float rowlim[128];
    unsigned long long best[128];
    int   wl[WLCAP];
    int   nitems, wtake;
};
#define ARG_SMEM_BYTES sizeof(ArgSmem)

__device__ __forceinline__ void stageE(ArgSmem* sm, int c, int t) {
    const char* gb = (const char*)g_embB + (size_t)(c << 6) * 128;
    #pragma unroll
    for (int it = 0; it < 2; ++it) {
        int id = it * 256 + t;          // 0..511 cells
        int code = id >> 3, h = id & 7;
        int cell = (code << 3) | (h ^ (code & 7));
        cp16(&sm->Es[c & 1][cell], gb + code * 128 + h * 16);
    }
}

// ---------------- argmin: MMA filter + exact rescore + fused enc ------------
__global__ void __launch_bounds__(256)
argmin_kernel(const float* __restrict__ inputs, float* __restrict__ out) {
    extern __shared__ char raw[];
    ArgSmem* sm = (ArgSmem*)raw;

    const float INF = __int_as_float(0x7f800000);
    const int t = threadIdx.x;
    const int lane = t & 31;
    const int w = t >> 5;               // 8 warps
    const int g = lane >> 2, tig = lane & 3;
    const int blk = blockIdx.x;         // 512 blocks of 128 rows
    const int b = blk >> 3, sp0 = (blk & 7) << 7;
    const float* xb = inputs + (size_t)b * 65536 + sp0;
    float2* encb = (float2*)(out + O_ENC) + (size_t)blk * 65536;  // this block's slice

    if (t < 128) sm->best[t] = 0xFFFFFFFFFFFFFFFFULL;
    if (t == 0) { sm->nitems = 0; sm->wtake = 0; }

    // X tile: Xs[r][d]
    #pragma unroll
    for (int it = 0; it < 8; ++it) {
        int id4 = it * 256 + t;         // 0..2047
        int d = id4 >> 5, rq = id4 & 31;
        float4 v = *(const float4*)(xb + d * 1024 + (rq << 2));
        sm->Xs[4 * rq + 0][d] = v.x;
        sm->Xs[4 * rq + 1][d] = v.y;
        sm->Xs[4 * rq + 2][d] = v.z;
        sm->Xs[4 * rq + 3][d] = v.w;
    }
    stageE(sm, 0, t);
    CP_COMMIT();
    __syncthreads();

    // A-fragments held in regs for whole phase 1
    const int R = w << 4;
    unsigned afr[16];
    {
        const float* r0 = sm->Xs[R + g];
        const float* r1 = sm->Xs[R + 8 + g];
        #pragma unroll
        for (int kk = 0; kk < 4; ++kk) {
            int c0 = 16 * kk + 2 * tig;
            afr[4 * kk + 0] = pack_bf16x2(r0[c0],     r0[c0 + 1]);
            afr[4 * kk + 1] = pack_bf16x2(r1[c0],     r1[c0 + 1]);
            afr[4 * kk + 2] = pack_bf16x2(r0[c0 + 8], r0[c0 + 9]);
            afr[4 * kk + 3] = pack_bf16x2(r1[c0 + 8], r1[c0 + 9]);
        }
    }
    // exact ||x||^2, reference rounding order
    if (t < 128) {
        float a = 0.f;
        #pragma unroll 16
        for (int d = 0; d < DIMD; ++d) {
            float v = sm->Xs[t][d];
            a = __fadd_rn(a, __fmul_rn(v, v));
        }
        sm->rowA[t] = a;
    }

    // -------- Phase 1: bf16 MMA filter + background enc zero-fill --------
    float sub_lo = INF, sub_hi = INF;
    for (int c = 0; c < 16; ++c) {
        CP_WAIT0();
        __syncthreads();
        if (c + 1 < 16) { stageE(sm, c + 1, t); CP_COMMIT(); }

        // background zero-fill: 1/16 of this block's one-hot slice, streaming
        {
            const float2 z = make_float2(0.f, 0.f);
            float2* zb = encb + (c << 12);
            #pragma unroll
            for (int it = 0; it < 16; ++it)
                __stcs(zb + it * 256 + t, z);
        }

        const uint4* Eb = sm->Es[c & 1];
        const int kc = c << 6;
        #pragma unroll
        for (int ct = 0; ct < 8; ++ct) {
            const int C = ct << 3;
            float c0 = 0.f, c1 = 0.f, c2 = 0.f, c3 = 0.f;
            #pragma unroll
            for (int kk2 = 0; kk2 < 2; ++kk2) {
                int code = C + (lane & 7);
                int h = (kk2 << 2) + (lane >> 3);
                unsigned q0, q1, q2, q3;
                ldsm4(q0, q1, q2, q3, Eb + ((code << 3) | (h ^ (code & 7))));
                mma16816(c0, c1, c2, c3, afr[8 * kk2 + 0], afr[8 * kk2 + 1],
                         afr[8 * kk2 + 2], afr[8 * kk2 + 3], q0, q1);
                mma16816(c0, c1, c2, c3, afr[8 * kk2 + 4], afr[8 * kk2 + 5],
                         afr[8 * kk2 + 6], afr[8 * kk2 + 7], q2, q3);
            }
            float B0 = __ldg(&g_B[kc + C + 2 * tig]);
            float B1 = __ldg(&g_B[kc + C + 2 * tig + 1]);
            float v0 = fmaf(-2.f, c0, B0);
            float v1 = fmaf(-2.f, c1, B1);
            float v2 = fmaf(-2.f, c2, B0);
            float v3 = fmaf(-2.f, c3, B1);
            sub_lo = fminf(sub_lo, fminf(v0, v1));
            sub_hi = fminf(sub_hi, fminf(v2, v3));
            if ((ct & 3) == 3) {
                sub_lo = fminf(sub_lo, __shfl_xor_sync(0xffffffffu, sub_lo, 1));
                sub_lo = fminf(sub_lo, __shfl_xor_sync(0xffffffffu, sub_lo, 2));
                sub_hi = fminf(sub_hi, __shfl_xor_sync(0xffffffffu, sub_hi, 1));
                sub_hi = fminf(sub_hi, __shfl_xor_sync(0xffffffffu, sub_hi, 2));
                int s = (c << 1) | (ct >> 2);
                if (tig == 0) {
                    sm->Cmin[s][R + g]     = sub_lo;
                    sm->Cmin[s][R + 8 + g] = sub_hi;
                }
                sub_lo = INF; sub_hi = INF;
            }
        }
        __syncthreads();   // protect Es buffer before next chunk's load overlaps
    }

    // -------- Phase 2: worklist + exact rescore (float4 codebook) --------
    if (t < 128) {
        float m = INF;
        #pragma unroll
        for (int s = 0; s < 32; ++s) m = fminf(m, sm->Cmin[s][t]);
        sm->rowlim[t] = m + MARGIN;
    }
    __syncthreads();
    if (t < 128) {
        float lim = sm->rowlim[t];
        #pragma unroll 4
        for (int s = 0; s < 32; ++s) {
            if (sm->Cmin[s][t] <= lim) {
                int pos = atomicAdd(&sm->nitems, 1);
                if (pos < WLCAP) {
                    sm->wl[pos] = (t << 5) | s;
                } else {
                    // overflow safety net: exact scalar rescore (inert normally)
                    for (int kk = 0; kk < 32; ++kk) {
                        int k = (s << 5) + kk;
                        float dot = 0.f;
                        for (int d = 0; d < DIMD; ++d)
                            dot = __fmaf_rn(sm->Xs[t][d], g_embT[(d << 10) + k], dot);
                        float dist = __fsub_rn(__fadd_rn(sm->rowA[t], g_B[k]),
                                               __fmul_rn(2.f, dot));
                        unsigned long long pkv =
                            ((unsigned long long)__float_as_uint(dist) << 32) | (unsigned)k;
                        atomicMin(&sm->best[t], pkv);
                    }
                }
            }
        }
    }
    __syncthreads();
    const int NI = min(sm->nitems, WLCAP);
    while (true) {
        int i = 0;
        if (lane == 0) i = atomicAdd(&sm->wtake, 1);
        i = __shfl_sync(0xffffffffu, i, 0);
        if (i >= NI) break;
        int item = sm->wl[i];
        int row = item >> 5, s = item & 31;
        int k = (s << 5) + lane;
        const float* xr = sm->Xs[row];
        float dot = 0.f;
        // sequential d order preserved: d = 4*d4 + {0,1,2,3}
        #pragma unroll
        for (int d4 = 0; d4 < 16; ++d4) {
            float4 e = __ldg(&g_embT4[(d4 << 10) + k]);
            dot = __fmaf_rn(xr[4 * d4 + 0], e.x, dot);
            dot = __fmaf_rn(xr[4 * d4 + 1], e.y, dot);
            dot = __fmaf_rn(xr[4 * d4 + 2], e.z, dot);
            dot = __fmaf_rn(xr[4 * d4 + 3], e.w, dot);
        }
        float dist = __fsub_rn(__fadd_rn(sm->rowA[row], g_B[k]), __fmul_rn(2.f, dot));
        unsigned long long pk = ((unsigned long long)__float_as_uint(dist) << 32) | (unsigned)k;
        #pragma unroll
        for (int off = 16; off > 0; off >>= 1) {
            unsigned long long o = __shfl_down_sync(0xffffffffu, pk, off);
            if (o < pk) pk = o;
        }
        if (lane == 0) atomicMin(&sm->best[row], pk);
    }
    __syncthreads();   // also orders the phase-1 zero stores before the ones below

    // -------- Epilogue: idx + hist + the 128 one-hot ones --------
    if (t < 128) {
        int k = (int)(unsigned)(sm->best[t] & 0xffffffffULL);
        int n = (blk << 7) + t;
        g_idx[n] = k;
        out[(size_t)O_IDX + n] = (float)k;
        atomicAdd(&g_hist[k], 1);
        out[(size_t)O_ENC + ((size_t)n << 10) + k] = 1.0f;
    }
}

// ---------------- quantized gather + MSE partials (scalar, coalesced) --------
__global__ void __launch_bounds__(256)
quant_kernel(const float* __restrict__ inputs, const float* __restrict__ emb,
             float* __restrict__ out) {
    const int base = blockIdx.x * 1024;
    float s = 0.f;
    #pragma unroll
    for (int i = 0; i < 4; ++i) {
        int e  = base + i * 256 + threadIdx.x;
        int sp = e & 1023;
        int d  = (e >> 10) & 63;
        int b  = e >> 16;
        int id = g_idx[(b << 10) + sp];
        float q = __ldg(&emb[id * DIMD + d]);
        float x = inputs[e];
        out[O_QUANT + e] = q;
        float df = q - x;
        s = __fmaf_rn(df, df, s);
    }
    #pragma unroll
    for (int off = 16; off > 0; off >>= 1)
        s += __shfl_down_sync(0xffffffffu, s, off);
    __shared__ float ws[8];
    if ((threadIdx.x & 31) == 0) ws[threadIdx.x >> 5] = s;
    __syncthreads();
    if (threadIdx.x == 0) {
        float tot = 0.f;
        #pragma unroll
        for (int i = 0; i < 8; ++i) tot += ws[i];
        g_partial[blockIdx.x] = tot;
    }
}

// ---------------- scalars: loss + perplexity ----------------
__global__ void __launch_bounds__(1024)
finalize_kernel(float* __restrict__ out) {
    __shared__ float ws[32];
    int t = threadIdx.x, lane = t & 31, w = t >> 5;
    float s = g_partial[t] + g_partial[t + 1024] + g_partial[t + 2048] + g_partial[t + 3072];
    #pragma unroll
    for (int off = 16; off > 0; off >>= 1) s += __shfl_down_sync(0xffffffffu, s, off);
    if (lane == 0) ws[w] = s;
    __syncthreads();
    if (t < 32) {
        float v = ws[t];
        #pragma unroll
        for (int off = 16; off > 0; off >>= 1) v += __shfl_down_sync(0xffffffffu, v, off);
        if (t == 0) ws[0] = v;
    }
    __syncthreads();
    float S = ws[0];
    __syncthreads();
    float p = (float)g_hist[t] * (1.0f / 65536.0f);
    float h = p * logf(p + 1e-10f);
    #pragma unroll
    for (int off = 16; off > 0; off >>= 1) h += __shfl_down_sync(0xffffffffu, h, off);
    if (lane == 0) ws[w] = h;
    __syncthreads();
    if (t < 32) {
        float v = ws[t];
        #pragma unroll
        for (int off = 16; off > 0; off >>= 1) v += __shfl_down_sync(0xffffffffu, v, off);
        if (t == 0) {
            float perp = expf(-v);
            float mse  = S * (1.0f / (float)QELEMS);
            float loss = __fadd_rn(mse, __fmul_rn(0.25f, mse));
            float dv   = __fdiv_rn(__fmul_rn(0.1f, __fsub_rn(1024.0f, perp)), 1024.0f);
            out[O_LOSS] = __fadd_rn(loss, dv);
            out[O_PERP] = perp;
        }
    }
}

// ---------------- launch ----------------
extern "C" void kernel_launch(void* const* d_in, const int* in_sizes, int n_in,
                              void* d_out, int out_size) {
    const float* inputs = (const float*)d_in[0];
    const float* emb    = (const float*)d_in[1];
    if (n_in >= 2 && in_sizes[0] == KCODES * DIMD) {
        inputs = (const float*)d_in[1];
        emb    = (const float*)d_in[0];
    }
    float* out = (float*)d_out;

    cudaFuncSetAttribute(argmin_kernel, cudaFuncAttributeMaxDynamicSharedMemorySize,
                         (int)ARG_SMEM_BYTES);

    prep_kernel<<<64, 256>>>(emb);
    argmin_kernel<<<512, 256, ARG_SMEM_BYTES>>>(inputs, out);
    quant_kernel<<<4096, 256>>>(inputs, emb, out);
    finalize_kernel<<<1, 1024>>>(out);
}

// round 12
// speedup vs baseline: 1.5170x; 1.0448x over previous
#include <cuda_runtime.h>
#include <cuda_bf16.h>
#include <cstdint>
#include <math.h>

// Problem constants
#define NROWS   65536
#define DIMD    64
#define KCODES  1024
#define QELEMS  4194304

// Output layout (float32, concatenated in reference return order)
#define O_LOSS  0
#define O_QUANT 1
#define O_PERP  4194305
#define O_ENC   4194306
#define O_IDX   71303170

#define MARGIN  1.5e-3f
#define WLCAP   1536

// ---------------- device scratch ----------------
__device__ float          g_embT[DIMD * KCODES];       // fp32 [d][k] (fallback path)
__device__ float4         g_embT4[16 * KCODES];        // fp32 [d4][k] -> 4 d's per LDG.128
__device__ __nv_bfloat16  g_embB[KCODES * DIMD];       // bf16 [k][d] for MMA filter
__device__ float          g_B[KCODES];                 // ||e_k||^2 exact order
__device__ __align__(16) int g_idx[NROWS];
__device__ int            g_hist[KCODES];
__device__ float          g_partial[512];

// ---------------- asm helpers ----------------
__device__ __forceinline__ unsigned pack_bf16x2(float lo, float hi) {
    unsigned r;
    asm("cvt.rn.bf16x2.f32 %0, %1, %2;" : "=r"(r) : "f"(hi), "f"(lo));
    return r;
}
__device__ __forceinline__ void mma16816(float& c0, float& c1, float& c2, float& c3,
                                         unsigned a0, unsigned a1, unsigned a2, unsigned a3,
                                         unsigned b0, unsigned b1) {
    asm("mma.sync.aligned.m16n8k16.row.col.f32.bf16.bf16.f32 "
        "{%0,%1,%2,%3},{%4,%5,%6,%7},{%8,%9},{%0,%1,%2,%3};"
        : "+f"(c0), "+f"(c1), "+f"(c2), "+f"(c3)
        : "r"(a0), "r"(a1), "r"(a2), "r"(a3), "r"(b0), "r"(b1));
}
__device__ __forceinline__ void ldsm4(unsigned& r0, unsigned& r1, unsigned& r2, unsigned& r3,
                                      const void* p) {
    unsigned a = (unsigned)__cvta_generic_to_shared(p);
    asm volatile("ldmatrix.sync.aligned.m8n8.x4.shared.b16 {%0,%1,%2,%3}, [%4];"
                 : "=r"(r0), "=r"(r1), "=r"(r2), "=r"(r3) : "r"(a));
}
__device__ __forceinline__ void cp16(void* sp, const void* gp) {
    unsigned a = (unsigned)__cvta_generic_to_shared(sp);
    asm volatile("cp.async.cg.shared.global [%0], [%1], 16;" :: "r"(a), "l"(gp));
}
#define CP_COMMIT() asm volatile("cp.async.commit_group;")
#define CP_WAIT0()  asm volatile("cp.async.wait_group 0;")

// ---------------- prep: transpose + bf16 pack + float4 layout + norms --------
__global__ void __launch_bounds__(256)
prep_kernel(const float* __restrict__ emb) {
    __shared__ float tile[16][65];
    const int t = threadIdx.x, b = blockIdx.x;      // 64 blocks, codes [16b,16b+16)
    const float* src = emb + b * 16 * DIMD;
    #pragma unroll
    for (int i = 0; i < 4; ++i) {
        int id = i * 256 + t;                 // 0..1023
        tile[id >> 6][id & 63] = src[id];
    }
    __syncthreads();
    // bf16 pack, linear layout identical to emb
    {
        __nv_bfloat162* dst = (__nv_bfloat162*)(g_embB + b * 1024);
        #pragma unroll
        for (int i = 0; i < 2; ++i) {
            int id2 = i * 256 + t;            // pair index 0..511
            int r = id2 >> 5, c2 = (id2 & 31) << 1;
            dst[id2] = __floats2bfloat162_rn(tile[r][c2], tile[r][c2 + 1]);
        }
    }
    // fp32 transpose: embT[d][16b + k]
    {
        int d = t >> 2, kq = (t & 3) << 2;
        float4 v;
        v.x = tile[kq + 0][d];
        v.y = tile[kq + 1][d];
        v.z = tile[kq + 2][d];
        v.w = tile[kq + 3][d];
        *(float4*)(g_embT + d * KCODES + b * 16 + kq) = v;
    }
    // float4 layout for rescore: embT4[d4][k] = emb[k][4d4..4d4+3]
    {
        int code = t & 15, d4 = t >> 4;       // 256 cells: coalesced over code
        float4 v;
        v.x = tile[code][4 * d4 + 0];
        v.y = tile[code][4 * d4 + 1];
        v.z = tile[code][4 * d4 + 2];
        v.w = tile[code][4 * d4 + 3];
        g_embT4[(d4 << 10) + b * 16 + code] = v;
    }
    // exact norms (sequential fl(e*e) adds)
    if (t < 16) {
        float s = 0.f;
        #pragma unroll 16
        for (int d = 0; d < DIMD; ++d) {
            float v = tile[t][d];
            s = __fadd_rn(s, __fmul_rn(v, v));
        }
        g_B[b * 16 + t] = s;
    }
    if (b == 0) {
        #pragma unroll
        for (int i = t; i < KCODES; i += 256) g_hist[i] = 0;
    }
}

// ---------------- argmin smem layout ----------------
struct ArgSmem {
    union {
        struct {
            uint4 Es[2][512];           // 16 KB swizzled bf16 E-chunk, dbl-buffered
            float Cmin[32][128];        // 16 KB per-subchunk approx min
        } p1;
        float Qs[128][65];              // epilogue: gathered codewords (33.3 KB)
    } u;
    float Xs[128][65];                  // fp32 X tile
    float rowA[128];
    float rowlim[128];
    unsigned long long best[128];
    int   idxs[128];
    int   wl[WLCAP];
    int   nitems, wtake;
};
#define ARG_SMEM_BYTES sizeof(ArgSmem)

__device__ __forceinline__ void stageE(ArgSmem* sm, int c, int t) {
    const char* gb = (const char*)g_embB + (size_t)(c << 6) * 128;
    #pragma unroll
    for (int it = 0; it < 2; ++it) {
        int id = it * 256 + t;          // 0..511 cells
        int code = id >> 3, h = id & 7;
        int cell = (code << 3) | (h ^ (code & 7));
        cp16(&sm->u.p1.Es[c & 1][cell], gb + code * 128 + h * 16);
    }
}

// ------- argmin: MMA filter + exact rescore + fused enc + fused quant -------
__global__ void __launch_bounds__(256)
argmin_kernel(const float* __restrict__ inputs, const float* __restrict__ emb,
              float* __restrict__ out) {
    extern __shared__ char raw[];
    ArgSmem* sm = (ArgSmem*)raw;
    __shared__ float ws[8];

    const float INF = __int_as_float(0x7f800000);
    const int t = threadIdx.x;
    const int lane = t & 31;
    const int w = t >> 5;               // 8 warps
    const int g = lane >> 2, tig = lane & 3;
    const int blk = blockIdx.x;         // 512 blocks of 128 rows
    const int b = blk >> 3, sp0 = (blk & 7) << 7;
    const float* xb = inputs + (size_t)b * 65536 + sp0;
    float2* encb = (float2*)(out + O_ENC) + (size_t)blk * 65536;  // this block's slice

    if (t < 128) sm->best[t] = 0xFFFFFFFFFFFFFFFFULL;
    if (t == 0) { sm->nitems = 0; sm->wtake = 0; }

    // X tile: Xs[r][d]
    #pragma unroll
    for (int it = 0; it < 8; ++it) {
        int id4 = it * 256 + t;         // 0..2047
        int d = id4 >> 5, rq = id4 & 31;
        float4 v = *(const float4*)(xb + d * 1024 + (rq << 2));
        sm->Xs[4 * rq + 0][d] = v.x;
        sm->Xs[4 * rq + 1][d] = v.y;
        sm->Xs[4 * rq + 2][d] = v.z;
        sm->Xs[4 * rq + 3][d] = v.w;
    }
    stageE(sm, 0, t);
    CP_COMMIT();
    __syncthreads();

    // A-fragments held in regs for whole phase 1
    const int R = w << 4;
    unsigned afr[16];
    {
        const float* r0 = sm->Xs[R + g];
        const float* r1 = sm->Xs[R + 8 + g];
        #pragma unroll
        for (int kk = 0; kk < 4; ++kk) {
            int c0 = 16 * kk + 2 * tig;
            afr[4 * kk + 0] = pack_bf16x2(r0[c0],     r0[c0 + 1]);
            afr[4 * kk + 1] = pack_bf16x2(r1[c0],     r1[c0 + 1]);
            afr[4 * kk + 2] = pack_bf16x2(r0[c0 + 8], r0[c0 + 9]);
            afr[4 * kk + 3] = pack_bf16x2(r1[c0 + 8], r1[c0 + 9]);
        }
    }
    // exact ||x||^2, reference rounding order
    if (t < 128) {
        float a = 0.f;
        #pragma unroll 16
        for (int d = 0; d < DIMD; ++d) {
            float v = sm->Xs[t][d];
            a = __fadd_rn(a, __fmul_rn(v, v));
        }
        sm->rowA[t] = a;
    }

    // -------- Phase 1: bf16 MMA filter + background enc zero-fill --------
    float sub_lo = INF, sub_hi = INF;
    for (int c = 0; c < 16; ++c) {
        CP_WAIT0();
        __syncthreads();
        if (c + 1 < 16) { stageE(sm, c + 1, t); CP_COMMIT(); }

        // background zero-fill: 1/16 of this block's one-hot slice, streaming
        {
            const float2 z = make_float2(0.f, 0.f);
            float2* zb = encb + (c << 12);
            #pragma unroll
            for (int it = 0; it < 16; ++it)
                __stcs(zb + it * 256 + t, z);
        }

        const uint4* Eb = sm->u.p1.Es[c & 1];
        const int kc = c << 6;
        #pragma unroll
        for (int ct = 0; ct < 8; ++ct) {
            const int C = ct << 3;
            float c0 = 0.f, c1 = 0.f, c2 = 0.f, c3 = 0.f;
            #pragma unroll
            for (int kk2 = 0; kk2 < 2; ++kk2) {
                int code = C + (lane & 7);
                int h = (kk2 << 2) + (lane >> 3);
                unsigned q0, q1, q2, q3;
                ldsm4(q0, q1, q2, q3, Eb + ((code << 3) | (h ^ (code & 7))));
                mma16816(c0, c1, c2, c3, afr[8 * kk2 + 0], afr[8 * kk2 + 1],
                         afr[8 * kk2 + 2], afr[8 * kk2 + 3], q0, q1);
                mma16816(c0, c1, c2, c3, afr[8 * kk2 + 4], afr[8 * kk2 + 5],
                         afr[8 * kk2 + 6], afr[8 * kk2 + 7], q2, q3);
            }
            float B0 = __ldg(&g_B[kc + C + 2 * tig]);
            float B1 = __ldg(&g_B[kc + C + 2 * tig + 1]);
            float v0 = fmaf(-2.f, c0, B0);
            float v1 = fmaf(-2.f, c1, B1);
            float v2 = fmaf(-2.f, c2, B0);
            float v3 = fmaf(-2.f, c3, B1);
            sub_lo = fminf(sub_lo, fminf(v0, v1));
            sub_hi = fminf(sub_hi, fminf(v2, v3));
            if ((ct & 3) == 3) {
                sub_lo = fminf(sub_lo, __shfl_xor_sync(0xffffffffu, sub_lo, 1));
                sub_lo = fminf(sub_lo, __shfl_xor_sync(0xffffffffu, sub_lo, 2));
                sub_hi = fminf(sub_hi, __shfl_xor_sync(0xffffffffu, sub_hi, 1));
                sub_hi = fminf(sub_hi, __shfl_xor_sync(0xffffffffu, sub_hi, 2));
                int s = (c << 1) | (ct >> 2);
                if (tig == 0) {
                    sm->u.p1.Cmin[s][R + g]     = sub_lo;
                    sm->u.p1.Cmin[s][R + 8 + g] = sub_hi;
                }
                sub_lo = INF; sub_hi = INF;
            }
        }
        __syncthreads();   // protect Es buffer before next chunk's load overlaps
    }

    // -------- Phase 2: worklist + exact rescore (float4 codebook) --------
    if (t < 128) {
        float m = INF;
        #pragma unroll
        for (int s = 0; s < 32; ++s) m = fminf(m, sm->u.p1.Cmin[s][t]);
        sm->rowlim[t] = m + MARGIN;
    }
    __syncthreads();
    if (t < 128) {
        float lim = sm->rowlim[t];
        #pragma unroll 4
        for (int s = 0; s < 32; ++s) {
            if (sm->u.p1.Cmin[s][t] <= lim) {
                int pos = atomicAdd(&sm->nitems, 1);
                if (pos < WLCAP) {
                    sm->wl[pos] = (t << 5) | s;
                } else {
                    // overflow safety net: exact scalar rescore (inert normally)
                    for (int kk = 0; kk < 32; ++kk) {
                        int k = (s << 5) + kk;
                        float dot = 0.f;
                        for (int d = 0; d < DIMD; ++d)
                            dot = __fmaf_rn(sm->Xs[t][d], g_embT[(d << 10) + k], dot);
                        float dist = __fsub_rn(__fadd_rn(sm->rowA[t], g_B[k]),
                                               __fmul_rn(2.f, dot));
                        unsigned long long pkv =
                            ((unsigned long long)__float_as_uint(dist) << 32) | (unsigned)k;
                        atomicMin(&sm->best[t], pkv);
                    }
                }
            }
        }
    }
    __syncthreads();
    const int NI = min(sm->nitems, WLCAP);
    while (true) {
        int i = 0;
        if (lane == 0) i = atomicAdd(&sm->wtake, 1);
        i = __shfl_sync(0xffffffffu, i, 0);
        if (i >= NI) break;
        int item = sm->wl[i];
        int row = item >> 5, s = item & 31;
        int k = (s << 5) + lane;
        const float* xr = sm->Xs[row];
        float dot = 0.f;
        // sequential d order preserved: d = 4*d4 + {0,1,2,3}
        #pragma unroll
        for (int d4 = 0; d4 < 16; ++d4) {
            float4 e = __ldg(&g_embT4[(d4 << 10) + k]);
            dot = __fmaf_rn(xr[4 * d4 + 0], e.x, dot);
            dot = __fmaf_rn(xr[4 * d4 + 1], e.y, dot);
            dot = __fmaf_rn(xr[4 * d4 + 2], e.z, dot);
            dot = __fmaf_rn(xr[4 * d4 + 3], e.w, dot);
        }
        float dist = __fsub_rn(__fadd_rn(sm->rowA[row], g_B[k]), __fmul_rn(2.f, dot));
        unsigned long long pk = ((unsigned long long)__float_as_uint(dist) << 32) | (unsigned)k;
        #pragma unroll
        for (int off = 16; off > 0; off >>= 1) {
            unsigned long long o = __shfl_down_sync(0xffffffffu, pk, off);
            if (o < pk) pk = o;
        }
        if (lane == 0) atomicMin(&sm->best[row], pk);
    }
    __syncthreads();   // orders phase-1 zero stores before ones; Cmin dead below

    // -------- Epilogue 1: idx + hist + the 128 one-hot ones --------
    if (t < 128) {
        int k = (int)(unsigned)(sm->best[t] & 0xffffffffULL);
        sm->idxs[t] = k;
        int n = (blk << 7) + t;
        g_idx[n] = k;
        out[(size_t)O_IDX + n] = (float)k;
        atomicAdd(&g_hist[k], 1);
        out[(size_t)O_ENC + ((size_t)n << 10) + k] = 1.0f;
    }
    __syncthreads();

    // -------- Epilogue 2: gather codewords into Qs (overlays Es/Cmin) --------
    #pragma unroll 8
    for (int it = 0; it < 32; ++it) {
        int id2 = it * 256 + t;         // 8192 = 128 rows x 64 d (coalesced over d)
        int row = id2 >> 6, d = id2 & 63;
        sm->u.Qs[row][d] = __ldg(&emb[sm->idxs[row] * DIMD + d]);
    }
    __syncthreads();

    // -------- Epilogue 3: quant NCHW write + MSE partial (32 KB stores) ------
    float acc = 0.f;
    {
        float* qout = out + O_QUANT + (size_t)b * 65536 + sp0;
        #pragma unroll 8
        for (int it = 0; it < 32; ++it) {
            int id3 = it * 256 + t;     // (d, row) layout -> coalesced over row
            int d = id3 >> 7, row = id3 & 127;
            float q = sm->u.Qs[row][d];
            float x = sm->Xs[row][d];
            qout[d * 1024 + row] = q;
            float df = q - x;
            acc = __fmaf_rn(df, df, acc);
        }
    }
    #pragma unroll
    for (int off = 16; off > 0; off >>= 1)
        acc += __shfl_down_sync(0xffffffffu, acc, off);
    if (lane == 0) ws[w] = acc;
    __syncthreads();
    if (t == 0) {
        float tot = 0.f;
        #pragma unroll
        for (int i = 0; i < 8; ++i) tot += ws[i];
        g_partial[blk] = tot;
    }
}

// ---------------- scalars: loss + perplexity ----------------
__global__ void __launch_bounds__(1024)
finalize_kernel(float* __restrict__ out) {
    __shared__ float ws[32];
    int t = threadIdx.x, lane = t & 31, w = t >> 5;
    float s = (t < 512) ? g_partial[t] : 0.f;
    #pragma unroll
    for (int off = 16; off > 0; off >>= 1) s += __shfl_down_sync(0xffffffffu, s, off);
    if (lane == 0) ws[w] = s;
    __syncthreads();
    if (t < 32) {
        float v = ws[t];
        #pragma unroll
        for (int off = 16; off > 0; off >>= 1) v += __shfl_down_sync(0xffffffffu, v, off);
        if (t == 0) ws[0] = v;
    }
    __syncthreads();
    float S = ws[0];
    __syncthreads();
    float p = (float)g_hist[t] * (1.0f / 65536.0f);
    float h = p * logf(p + 1e-10f);
    #pragma unroll
    for (int off = 16; off > 0; off >>= 1) h += __shfl_down_sync(0xffffffffu, h, off);
    if (lane == 0) ws[w] = h;
    __syncthreads();
    if (t < 32) {
        float v = ws[t];
        #pragma unroll
        for (int off = 16; off > 0; off >>= 1) v += __shfl_down_sync(0xffffffffu, v, off);
        if (t == 0) {
            float perp = expf(-v);
            float mse  = S * (1.0f / (float)QELEMS);
            float loss = __fadd_rn(mse, __fmul_rn(0.25f, mse));
            float dv   = __fdiv_rn(__fmul_rn(0.1f, __fsub_rn(1024.0f, perp)), 1024.0f);
            out[O_LOSS] = __fadd_rn(loss, dv);
            out[O_PERP] = perp;
        }
    }
}

// ---------------- launch ----------------
extern "C" void kernel_launch(void* const* d_in, const int* in_sizes, int n_in,
                              void* d_out, int out_size) {
    const float* inputs = (const float*)d_in[0];
    const float* emb    = (const float*)d_in[1];
    if (n_in >= 2 && in_sizes[0] == KCODES * DIMD) {
        inputs = (const float*)d_in[1];
        emb    = (const float*)d_in[0];
    }
    float* out = (float*)d_out;

    cudaFuncSetAttribute(argmin_kernel, cudaFuncAttributeMaxDynamicSharedMemorySize,
                         (int)ARG_SMEM_BYTES);

    prep_kernel<<<64, 256>>>(emb);
    argmin_kernel<<<512, 256, ARG_SMEM_BYTES>>>(inputs, emb, out);
    finalize_kernel<<<1, 1024>>>(out);
}